// round 17
// baseline (speedup 1.0000x reference)
#include <cuda_runtime.h>
#include <cuda_fp16.h>

#define NN   100000
#define NE   1200000
#define DIM  64
#define NL   3
#define NG   256
#define RHID 128
#define ROUT 32

#define SCAN_CHUNK 1024
#define NB_SCAN ((NN + SCAN_CHUNK - 1) / SCAN_CHUNK)   // 98

#define NTILES ((NN + 63) / 64)       // 1563
#define PGRID  740                    // 148 SMs x 5 blocks

// Scratch (__device__ globals: allocation-guard safe)
__device__ __half d_hx[NN * DIM];            // fp16 copy of x (12.8 MB)
__device__ __half d_h[NL][NN * DIM];         // 38.4 MB
__device__ float  d_g[NG * NL * DIM];        // 192 KB
__device__ int    d_deg[NN];
__device__ int    d_rowptr[NN];
__device__ int    d_cursor[NN];
__device__ int    d_csrc[NE];
__device__ int    d_blocksum[128];

// ---------------------------------------------------------------------------
// Zero deg + g in one launch
// ---------------------------------------------------------------------------
__global__ void zero_misc_kernel() {
    int i = blockIdx.x * blockDim.x + threadIdx.x;
    if (i < NN) d_deg[i] = 0;
    if (i < NG * NL * DIM) d_g[i] = 0.f;
}

// ---------------------------------------------------------------------------
// Fused histogram + x->fp16 conversion (independent work, one launch)
// ---------------------------------------------------------------------------
__global__ void hist_convert_kernel(const int* __restrict__ dst,
                                    const float* __restrict__ x) {
    int i = blockIdx.x * blockDim.x + threadIdx.x;
    if (i < NE) atomicAdd(&d_deg[dst[i]], 1);
    if (i < NN * DIM / 4) {
        float4 v = reinterpret_cast<const float4*>(x)[i];
        __half2 lo = __floats2half2_rn(v.x, v.y);
        __half2 hi = __floats2half2_rn(v.z, v.w);
        reinterpret_cast<uint2*>(d_hx)[i] =
            make_uint2(*reinterpret_cast<unsigned*>(&lo), *reinterpret_cast<unsigned*>(&hi));
    }
}

// ---------------------------------------------------------------------------
// CSR build: 2-level exclusive scan -> cursor fill
// ---------------------------------------------------------------------------
__global__ void bsum_kernel() {               // grid = NB_SCAN, 256 thr
    __shared__ int ssum[256];
    int b = blockIdx.x, t = threadIdx.x;
    int base = b * SCAN_CHUNK;
    int s = 0;
    for (int i = t; i < SCAN_CHUNK; i += 256) {
        int idx = base + i;
        if (idx < NN) s += d_deg[idx];
    }
    ssum[t] = s; __syncthreads();
    for (int o = 128; o > 0; o >>= 1) {
        if (t < o) ssum[t] += ssum[t + o];
        __syncthreads();
    }
    if (t == 0) d_blocksum[b] = ssum[0];
}

__global__ void scan_bsums_kernel() {         // 1 block, 128 thr
    __shared__ int sb[128];
    int t = threadIdx.x;
    int v = (t < NB_SCAN) ? d_blocksum[t] : 0;
    sb[t] = v; __syncthreads();
    for (int o = 1; o < 128; o <<= 1) {
        int add = (t >= o) ? sb[t - o] : 0;
        __syncthreads();
        sb[t] += add;
        __syncthreads();
    }
    if (t < NB_SCAN) d_blocksum[t] = sb[t] - v;   // exclusive
}

__global__ void scan_chunks_kernel() {        // grid = NB_SCAN, 256 thr
    __shared__ int tsum[256];
    int b = blockIdx.x, t = threadIdx.x;
    int base = b * SCAN_CHUNK;
    int idx0 = base + t * 4;
    int v[4], s = 0;
#pragma unroll
    for (int j = 0; j < 4; j++) {
        int idx = idx0 + j;
        v[j] = (idx < NN) ? d_deg[idx] : 0;
        s += v[j];
    }
    tsum[t] = s; __syncthreads();
    int mine = s;
    for (int o = 1; o < 256; o <<= 1) {
        int add = (t >= o) ? tsum[t - o] : 0;
        __syncthreads();
        tsum[t] += add;
        __syncthreads();
    }
    int run = tsum[t] - mine + d_blocksum[b];
#pragma unroll
    for (int j = 0; j < 4; j++) {
        int idx = idx0 + j;
        if (idx < NN) { d_rowptr[idx] = run; d_cursor[idx] = run; run += v[j]; }
    }
}

__global__ void fill_kernel(const int* __restrict__ src,
                            const int* __restrict__ dst) {
    int e = blockIdx.x * blockDim.x + threadIdx.x;
    if (e < NE) {
        int p = atomicAdd(&d_cursor[dst[e]], 1);
        d_csrc[p] = src[e];
    }
}

// ---------------------------------------------------------------------------
// Fused GIN layer: persistent blocks (5/SM), paired-neighbor gather, FFMA gemm.
// Occupancy raised 4 -> 5 blocks/SM (40 warps) to cover L2 gather latency
// and widen cross-block gather/gemm overlap — the surviving bottleneck theory
// after R14-R16 eliminated math, index-latency, and issue-count.
// ---------------------------------------------------------------------------
#define INS_PAD 68

__global__ void __launch_bounds__(256, 5)
gin_layer_kernel(const float* __restrict__ gW,
                 const float* __restrict__ gB,
                 const float* __restrict__ eps, int layer) {
    __shared__ float Ws[DIM * DIM];          // 16 KB
    __shared__ float ins[64 * INS_PAD];      // 17.4 KB

    const __half* __restrict__ hp = (layer == 0) ? d_hx : d_h[layer - 1];
    int t    = threadIdx.x;
    int warp = t >> 5, lane = t & 31;
    int h    = lane >> 4;                    // half-warp id (neighbor parity)
    int q    = lane & 15;                    // col quad: cols 4q..4q+3

    // Stage W once per block
    const float4* Wg = reinterpret_cast<const float4*>(gW + layer * DIM * DIM);
    float4* Wsv = reinterpret_cast<float4*>(Ws);
    for (int i = t; i < DIM * DIM / 4; i += 256) Wsv[i] = Wg[i];

    float e1 = 1.0f + eps[layer];
    int tx = t & 15;          // gemm: cols 4tx..4tx+3
    int ty = t >> 4;          // gemm: nodes 4ty..4ty+3
    const float* b4 = gB + layer * DIM + 4 * tx;
    float bx = b4[0], by = b4[1], bz = b4[2], bw = b4[3];
    __half* hl = d_h[layer];

    for (int tile = blockIdx.x; tile < NTILES; tile += PGRID) {
        int n0 = tile * 64;
        __syncthreads();                     // ins safe to overwrite

        // ---- Phase 1: gather (warp per node, paired neighbor loads) ----
#pragma unroll
        for (int i = 0; i < 8; i++) {
            int nl = warp * 8 + i;           // local node 0..63
            int n  = n0 + nl;
            float a0 = 0.f, a1 = 0.f, a2 = 0.f, a3 = 0.f;
            if (n < NN) {                    // warp-uniform
                uint2 own = *reinterpret_cast<const uint2*>(hp + (size_t)n * DIM + 4 * q);
                {
                    float2 f0 = __half22float2(*reinterpret_cast<__half2*>(&own.x));
                    float2 f1 = __half22float2(*reinterpret_cast<__half2*>(&own.y));
                    float sc = (h == 0) ? e1 : 0.f;
                    a0 = sc * f0.x; a1 = sc * f0.y; a2 = sc * f1.x; a3 = sc * f1.y;
                }
                int beg = d_rowptr[n];
                int deg = d_deg[n];
                for (int chunk = 0; chunk < deg; chunk += 32) {
                    int cnt = deg - chunk; if (cnt > 32) cnt = 32;
                    int myidx = (lane < cnt) ? d_csrc[beg + chunk + lane] : 0;
                    int e = 0;
                    for (; e + 8 <= cnt; e += 8) {     // 8 neighbors = 4 paired loads
                        uint2 v[4];
#pragma unroll
                        for (int j = 0; j < 4; j++) {
                            int s = __shfl_sync(0xffffffffu, myidx, e + 2 * j + h);
                            v[j] = *reinterpret_cast<const uint2*>(hp + (size_t)s * DIM + 4 * q);
                        }
#pragma unroll
                        for (int j = 0; j < 4; j++) {
                            float2 f0 = __half22float2(*reinterpret_cast<__half2*>(&v[j].x));
                            float2 f1 = __half22float2(*reinterpret_cast<__half2*>(&v[j].y));
                            a0 += f0.x; a1 += f0.y; a2 += f1.x; a3 += f1.y;
                        }
                    }
                    for (; e < cnt; e += 2) {          // remainder, paired
                        int ei = e + h;
                        int s = __shfl_sync(0xffffffffu, myidx, (ei < cnt) ? ei : e);
                        if (ei < cnt) {
                            uint2 v = *reinterpret_cast<const uint2*>(hp + (size_t)s * DIM + 4 * q);
                            float2 f0 = __half22float2(*reinterpret_cast<__half2*>(&v.x));
                            float2 f1 = __half22float2(*reinterpret_cast<__half2*>(&v.y));
                            a0 += f0.x; a1 += f0.y; a2 += f1.x; a3 += f1.y;
                        }
                    }
                }
                a0 += __shfl_xor_sync(0xffffffffu, a0, 16);
                a1 += __shfl_xor_sync(0xffffffffu, a1, 16);
                a2 += __shfl_xor_sync(0xffffffffu, a2, 16);
                a3 += __shfl_xor_sync(0xffffffffu, a3, 16);
            }
            if (h == 0)
                *reinterpret_cast<float4*>(&ins[nl * INS_PAD + 4 * q]) =
                    make_float4(a0, a1, a2, a3);
        }
        __syncthreads();

        // ---- Phase 2: 4x4 register-blocked gemm + bias + ReLU -> fp16 ----
        float4 acc0 = make_float4(bx, by, bz, bw);
        float4 acc1 = acc0, acc2 = acc0, acc3 = acc0;

        const float* ir0 = &ins[(4 * ty + 0) * INS_PAD];
        const float* ir1 = &ins[(4 * ty + 1) * INS_PAD];
        const float* ir2 = &ins[(4 * ty + 2) * INS_PAD];
        const float* ir3 = &ins[(4 * ty + 3) * INS_PAD];

#pragma unroll 8
        for (int k = 0; k < DIM; k++) {
            float4 w = *reinterpret_cast<const float4*>(&Ws[k * DIM + 4 * tx]);
            float a0 = ir0[k], a1 = ir1[k], a2 = ir2[k], a3 = ir3[k];
            acc0.x = fmaf(a0, w.x, acc0.x); acc0.y = fmaf(a0, w.y, acc0.y);
            acc0.z = fmaf(a0, w.z, acc0.z); acc0.w = fmaf(a0, w.w, acc0.w);
            acc1.x = fmaf(a1, w.x, acc1.x); acc1.y = fmaf(a1, w.y, acc1.y);
            acc1.z = fmaf(a1, w.z, acc1.z); acc1.w = fmaf(a1, w.w, acc1.w);
            acc2.x = fmaf(a2, w.x, acc2.x); acc2.y = fmaf(a2, w.y, acc2.y);
            acc2.z = fmaf(a2, w.z, acc2.z); acc2.w = fmaf(a2, w.w, acc2.w);
            acc3.x = fmaf(a3, w.x, acc3.x); acc3.y = fmaf(a3, w.y, acc3.y);
            acc3.z = fmaf(a3, w.z, acc3.z); acc3.w = fmaf(a3, w.w, acc3.w);
        }

#pragma unroll
        for (int i = 0; i < 4; i++) {
            int n = n0 + 4 * ty + i;
            if (n < NN) {
                float4 a = (i == 0) ? acc0 : (i == 1) ? acc1 : (i == 2) ? acc2 : acc3;
                __half2 lo = __floats2half2_rn(fmaxf(a.x, 0.f), fmaxf(a.y, 0.f));
                __half2 hi = __floats2half2_rn(fmaxf(a.z, 0.f), fmaxf(a.w, 0.f));
                reinterpret_cast<uint2*>(hl + (size_t)n * DIM + 4 * tx)[0] =
                    make_uint2(*reinterpret_cast<unsigned*>(&lo), *reinterpret_cast<unsigned*>(&hi));
            }
        }
    }
}

// ---------------------------------------------------------------------------
// Readout: segmented running sum over sorted graph_ids (fp16 in, fp32 accum).
// ---------------------------------------------------------------------------
#define RO_CHUNK 128
__global__ void readout_kernel(const int* __restrict__ gid) {
    int t   = threadIdx.x;                    // 0..191
    int lay = t >> 6, col = t & 63;
    int n0  = blockIdx.x * RO_CHUNK;
    int nend = min(n0 + RO_CHUNK, NN);
    const __half* __restrict__ hp = d_h[lay];

    float acc = 0.f;
    int cur = gid[n0];
    for (int n = n0; n < nend; n++) {
        int gi = gid[n];
        if (gi != cur) {
            atomicAdd(&d_g[cur * (NL * DIM) + t], acc);
            acc = 0.f;
            cur = gi;
        }
        acc += __half2float(hp[(size_t)n * DIM + col]);
    }
    atomicAdd(&d_g[cur * (NL * DIM) + t], acc);
}

// ---------------------------------------------------------------------------
// Readout MLP
// ---------------------------------------------------------------------------
__global__ void mlp_kernel(const float* __restrict__ W1, const float* __restrict__ b1,
                           const float* __restrict__ W2, const float* __restrict__ b2,
                           float* __restrict__ out) {
    int b = blockIdx.x, t = threadIdx.x;      // 192 threads
    __shared__ float gv[NL * DIM];
    __shared__ float hid[RHID];

    gv[t] = d_g[b * (NL * DIM) + t];
    __syncthreads();

    if (t < RHID) {
        float acc = b1[t];
#pragma unroll 4
        for (int k = 0; k < NL * DIM; k++)
            acc = fmaf(gv[k], W1[k * RHID + t], acc);
        hid[t] = fmaxf(acc, 0.f);
    }
    __syncthreads();

    if (t < ROUT) {
        float acc = b2[t];
#pragma unroll 4
        for (int k = 0; k < RHID; k++)
            acc = fmaf(hid[k], W2[k * ROUT + t], acc);
        out[b * ROUT + t] = acc;
    }
}

// ---------------------------------------------------------------------------
extern "C" void kernel_launch(void* const* d_in, const int* in_sizes, int n_in,
                              void* d_out, int out_size) {
    const float* x   = (const float*)d_in[0];
    const float* gW  = (const float*)d_in[1];
    const float* gB  = (const float*)d_in[2];
    const float* eps = (const float*)d_in[3];
    const float* rW1 = (const float*)d_in[4];
    const float* rb1 = (const float*)d_in[5];
    const float* rW2 = (const float*)d_in[6];
    const float* rb2 = (const float*)d_in[7];
    const int*   src = (const int*)d_in[8];
    const int*   dst = (const int*)d_in[9];
    const int*   gid = (const int*)d_in[10];
    float* out = (float*)d_out;

    // CSR build + x conversion (once per launch)
    zero_misc_kernel<<<(NN + 255) / 256, 256>>>();
    hist_convert_kernel<<<(NN * DIM / 4 + 255) / 256, 256>>>(dst, x);
    bsum_kernel<<<NB_SCAN, 256>>>();
    scan_bsums_kernel<<<1, 128>>>();
    scan_chunks_kernel<<<NB_SCAN, 256>>>();
    fill_kernel<<<(NE + 255) / 256, 256>>>(src, dst);

    for (int l = 0; l < NL; l++)
        gin_layer_kernel<<<PGRID, 256>>>(gW, gB, eps, l);

    readout_kernel<<<(NN + RO_CHUNK - 1) / RO_CHUNK, 192>>>(gid);
    mlp_kernel<<<NG, 192>>>(rW1, rb1, rW2, rb2, out);
}